// round 12
// baseline (speedup 1.0000x reference)
#include <cuda_runtime.h>
#include <cuda_fp16.h>
#include <cstdint>
#include <math.h>

#define BATCH 64
#define ONUM  32
#define INUM  512
#define DD    64
#define OD    2048               // ONUM*DD

// ---------------- scratch (device globals) -----------------------------------
__device__ __half g_xhat[(size_t)BATCH * INUM * OD];   // [b][i][o][d] fp16, 134MB
__device__ float g_s[3][BATCH * OD];
__device__ float g_b1[(size_t)BATCH * INUM * ONUM];    // permuted: [b][i][g*8+c]

// ---------------- helpers -----------------------------------------------------
__device__ __forceinline__ uint32_t smem_u32(const void* p) {
    uint32_t a;
    asm("{ .reg .u64 t; cvta.to.shared.u64 t, %1; cvt.u32.u64 %0, t; }" : "=r"(a) : "l"(p));
    return a;
}
__device__ __forceinline__ uint2 f4_to_h4(float4 v) {
    __half2 h0 = __floats2half2_rn(v.x, v.y);
    __half2 h1 = __floats2half2_rn(v.z, v.w);
    return make_uint2(*(uint32_t*)&h0, *(uint32_t*)&h1);
}
__device__ __forceinline__ uint32_t f2_to_h2(float a, float b) {
    __half2 h = __floats2half2_rn(a, b);
    return *(uint32_t*)&h;
}
__device__ __forceinline__ void ldmx4(uint32_t* r, uint32_t addr) {
    asm volatile("ldmatrix.sync.aligned.m8n8.x4.shared.b16 {%0,%1,%2,%3}, [%4];"
                 : "=r"(r[0]), "=r"(r[1]), "=r"(r[2]), "=r"(r[3]) : "r"(addr));
}
__device__ __forceinline__ void mma16816(float* c, const uint32_t* a, uint32_t b0, uint32_t b1) {
    asm volatile("mma.sync.aligned.m16n8k16.row.col.f32.f16.f16.f32 "
                 "{%0,%1,%2,%3}, {%4,%5,%6,%7}, {%8,%9}, {%0,%1,%2,%3};"
                 : "+f"(c[0]), "+f"(c[1]), "+f"(c[2]), "+f"(c[3])
                 : "r"(a[0]), "r"(a[1]), "r"(a[2]), "r"(a[3]), "r"(b0), "r"(b1));
}
__device__ __forceinline__ void cp16(uint32_t dst, const void* src) {
    asm volatile("cp.async.cg.shared.global [%0], [%1], 16;" :: "r"(dst), "l"(src));
}
#define CP_COMMIT() asm volatile("cp.async.commit_group;" ::: "memory")
#define CP_WAIT1()  asm volatile("cp.async.wait_group 1;" ::: "memory")

// ---------------- zero --------------------------------------------------------
__global__ void zero_s_kernel() {
    int idx = blockIdx.x * blockDim.x + threadIdx.x;
    if (idx < 3 * BATCH * OD) (&g_s[0][0])[idx] = 0.0f;
}

// ---------------- HMMA GEMM: x_hat + fused s0 (at DRAM roofline) --------------
#define WT_S 72
#define XT_S 72
#define OT_S 136

__global__ __launch_bounds__(256, 2) void gemm_xhat_hmma(
    const float* __restrict__ x, const float* __restrict__ w)
{
    __shared__ __align__(16) __half Wt[128 * WT_S];  // [od][m]
    __shared__ __align__(16) __half Xt[64 * XT_S];   // [b][m]
    __shared__ __align__(16) __half Ot[64 * OT_S];   // [b][od 0..127]

    const int tid = threadIdx.x, wid = tid >> 5, lane = tid & 31;
    const int p = blockIdx.x;
    const int ibase = blockIdx.y * 16;

    const uint32_t wbase = smem_u32(Wt);
    const uint32_t xbase = smem_u32(Xt);

    const float4* wf4 = (const float4*)w;
    const float4* xf4 = (const float4*)x;

    const int wm = wid & 1;
    const int wn = wid >> 1;
    const int r0a = wm * 32;
    const int n0  = wn * 32;

    const int a_row_off = (lane & 7) + ((lane >> 3) & 1) * 8;
    const int a_col_off = (lane >= 16) ? 8 : 0;
    const int b_row_off = (lane & 7) + ((lane >> 4) & 1) * 8;
    const int b_col_off = ((lane >> 3) & 1) * 8;

    float s0acc[4][8];
#pragma unroll
    for (int j = 0; j < 4; j++)
#pragma unroll
        for (int e = 0; e < 8; e++) s0acc[j][e] = 0.0f;

    for (int t = 0; t < 16; t++) {
        const int i = ibase + t;

#pragma unroll
        for (int k = 0; k < 8; k++) {
            int g = tid + k * 256;
            int ol = g >> 10, rem = g & 1023;
            float4 v = wf4[(((size_t)(2 * p + ol) * INUM + i) << 10) + rem];
            *(uint2*)&Wt[(ol * 64 + (rem >> 4)) * WT_S + (rem & 15) * 4] = f4_to_h4(v);
        }
#pragma unroll
        for (int j = 0; j < 4; j++) {
            int idx = tid + j * 256;
            int b = idx >> 4, mq = idx & 15;
            float4 v = xf4[((size_t)b * INUM + i) * 16 + mq];
            *(uint2*)&Xt[b * XT_S + mq * 4] = f4_to_h4(v);
        }
        __syncthreads();

        float acc[2][4][4];
#pragma unroll
        for (int mt = 0; mt < 2; mt++)
#pragma unroll
            for (int nt = 0; nt < 4; nt++)
#pragma unroll
                for (int e = 0; e < 4; e++) acc[mt][nt][e] = 0.0f;

#pragma unroll
        for (int ks = 0; ks < 4; ks++) {
            const int kc = ks * 16;
            uint32_t afr[2][4], bfr[2][4];
#pragma unroll
            for (int mt = 0; mt < 2; mt++) {
                int row = r0a + mt * 16 + a_row_off;
                int col = kc + a_col_off;
                ldmx4(afr[mt], xbase + (row * XT_S + col) * 2);
            }
#pragma unroll
            for (int nt2 = 0; nt2 < 2; nt2++) {
                int row = n0 + nt2 * 16 + b_row_off;
                int col = kc + b_col_off;
                ldmx4(bfr[nt2], wbase + (row * WT_S + col) * 2);
            }
#pragma unroll
            for (int mt = 0; mt < 2; mt++) {
#pragma unroll
                for (int nt = 0; nt < 4; nt++) {
                    uint32_t b0 = bfr[nt >> 1][(nt & 1) * 2 + 0];
                    uint32_t b1 = bfr[nt >> 1][(nt & 1) * 2 + 1];
                    mma16816(acc[mt][nt], afr[mt], b0, b1);
                }
            }
        }

#pragma unroll
        for (int mt = 0; mt < 2; mt++) {
            int row = r0a + mt * 16 + (lane >> 2);
#pragma unroll
            for (int nt = 0; nt < 4; nt++) {
                int col = n0 + nt * 8 + (lane & 3) * 2;
                *(uint32_t*)&Ot[row * OT_S + col] = f2_to_h2(acc[mt][nt][0], acc[mt][nt][1]);
                *(uint32_t*)&Ot[(row + 8) * OT_S + col] = f2_to_h2(acc[mt][nt][2], acc[mt][nt][3]);
            }
        }
        __syncthreads();

#pragma unroll
        for (int j = 0; j < 4; j++) {
            int idx = tid + j * 256;
            int brow = idx >> 4, chunk = idx & 15;
            uint4 v = *(const uint4*)&Ot[brow * OT_S + chunk * 8];
            const __half2* h = (const __half2*)&v;
#pragma unroll
            for (int q = 0; q < 4; q++) {
                float2 f = __half22float2(h[q]);
                s0acc[j][q * 2 + 0] += f.x;
                s0acc[j][q * 2 + 1] += f.y;
            }
            *(uint4*)&g_xhat[((size_t)brow * INUM + i) * OD + p * 128 + chunk * 8] = v;
        }
        __syncthreads();
    }

    const float sc = 1.0f / (float)ONUM;
#pragma unroll
    for (int j = 0; j < 4; j++) {
        int idx = tid + j * 256;
        int brow = idx >> 4, chunk = idx & 15;
        float* sp = &g_s[0][brow * OD + p * 128 + chunk * 8];
#pragma unroll
        for (int e = 0; e < 8; e++)
            atomicAdd(sp + e, s0acc[j][e] * sc);
    }
}

// ---------------- final squash ------------------------------------------------
__global__ void squash_kernel(const float* __restrict__ s, float* __restrict__ v)
{
    int gw   = (blockIdx.x * blockDim.x + threadIdx.x) >> 5;
    int lane = threadIdx.x & 31;
    if (gw >= BATCH * ONUM) return;
    const float* row = s + (size_t)gw * 64;
    float a = row[lane];
    float b = row[lane + 32];
    float ss = a * a + b * b;
#pragma unroll
    for (int off = 16; off; off >>= 1) ss += __shfl_xor_sync(0xffffffffu, ss, off);
    float n = sqrtf(ss);
    float f = (ss / (1.0f + ss)) / (n + 1e-8f);
    v[(size_t)gw * 64 + lane]      = a * f;
    v[(size_t)gw * 64 + lane + 32] = b * f;
}

// ---------------- routing pass v11 --------------------------------------------
// grid (64,8), block 128 (4 warps), 16 i/warp, 3 CTAs/SM target (regs <= 166).
// Coalesced cp.async 3-stage ring (lead 2); opv in smem fp16 (conflict-free
// LDS.128); chunks streamed from ring (no cur[] registers); inline squash of
// s_prev in prologue; group-shuffle dot; max-free softmax; b1 prefetch.
#define RING_BYTES (4 * 3 * 4096)            // 49152
#define OPSH_S 72                            // halves per o row (144B)
#define RED_S  65
#define OPSH_OFF RING_BYTES
#define RED_OFF  (RING_BYTES + ONUM * OPSH_S * 2)
#define ROUTE_SMEM (RED_OFF + ONUM * RED_S * 4)

template <int MODE>
__global__ __launch_bounds__(128, 3) void route_v11(
    const float* __restrict__ s_prev, float* __restrict__ s_next)
{
    extern __shared__ __align__(16) char dsm[];
    __half* opsh = (__half*)(dsm + OPSH_OFF);
    float*  red  = (float*)(dsm + RED_OFF);

    const int tid = threadIdx.x, wid = tid >> 5, lane = tid & 31;
    const int g = lane >> 3, m = lane & 7;
    const int b = blockIdx.x;
    const int i0 = (blockIdx.y * 4 + wid) * 16;

    const uint4* xp = (const uint4*)(g_xhat + ((size_t)b * INUM + i0) * OD);
    const uint32_t ringbase = smem_u32(dsm) + wid * (3 * 4096);
    const char* ringptr = dsm + wid * (3 * 4096);

    // issue first 2 stages (coalesced 512B per instr both sides)
#pragma unroll
    for (int t = 0; t < 2; t++) {
        const uint4* src = xp + t * 256;
        uint32_t dst = ringbase + t * 4096;
#pragma unroll
        for (int c = 0; c < 8; c++)
            cp16(dst + (c * 32 + lane) * 16, src + c * 32 + lane);
        CP_COMMIT();
    }

    // inline squash: opsh[o][d] = squash(s_prev[b])[o][d] (fp16); warp: 8 rows
#pragma unroll
    for (int r = 0; r < 8; r++) {
        int row = wid * 8 + r;
        float a  = s_prev[(size_t)b * OD + row * 64 + lane];
        float c2 = s_prev[(size_t)b * OD + row * 64 + lane + 32];
        float ss = a * a + c2 * c2;
#pragma unroll
        for (int off = 16; off; off >>= 1) ss += __shfl_xor_sync(0xffffffffu, ss, off);
        float n = sqrtf(ss);
        float f = (ss / (1.0f + ss)) / (n + 1e-8f);
        opsh[row * OPSH_S + lane]      = __float2half_rn(a * f);
        opsh[row * OPSH_S + lane + 32] = __float2half_rn(c2 * f);
    }
    for (int k = tid; k < ONUM * RED_S; k += 128) red[k] = 0.0f;
    __syncthreads();

    float sacc[64];
#pragma unroll
    for (int d = 0; d < 64; d++) sacc[d] = 0.0f;

    float* b1t = g_b1 + ((size_t)b * INUM + i0) * ONUM;   // [i][g*8+c]
    float4 b1a, b1b;
    if (MODE == 1) {
        b1a = *(const float4*)(b1t + g * 8);
        b1b = *(const float4*)(b1t + g * 8 + 4);
    }

    for (int ii = 0; ii < 16; ii++) {
        CP_WAIT1();   // 2-pending invariant -> stage ii complete

        const uint4* stg = (const uint4*)(ringptr + (ii % 3) * 4096);

        // issue stage ii+2 (dummy commit keeps pending invariant)
        if (ii + 2 < 16) {
            const uint4* src = xp + (size_t)(ii + 2) * 256;
            uint32_t dst = ringbase + ((ii + 2) % 3) * 4096;
#pragma unroll
            for (int c = 0; c < 8; c++)
                cp16(dst + (c * 32 + lane) * 16, src + c * 32 + lane);
        }
        CP_COMMIT();

        // partial dots pd[c] = <chunk c, opv[c]>; both streamed from smem
        float pd[8];
#pragma unroll
        for (int c = 0; c < 8; c++) {
            uint4 xv = stg[c * 32 + lane];
            uint4 ov = *(const uint4*)&opsh[(c * 4 + g) * OPSH_S + m * 8];
            const __half2* h = (const __half2*)&xv;
            const __half2* o = (const __half2*)&ov;
            float2 f0 = __half22float2(h[0]), o0 = __half22float2(o[0]);
            float2 f1 = __half22float2(h[1]), o1 = __half22float2(o[1]);
            float2 f2 = __half22float2(h[2]), o2 = __half22float2(o[2]);
            float2 f3 = __half22float2(h[3]), o3 = __half22float2(o[3]);
            pd[c] = f0.x * o0.x + f0.y * o0.y + f1.x * o1.x + f1.y * o1.y
                  + f2.x * o2.x + f2.y * o2.y + f3.x * o3.x + f3.y * o3.y;
        }
        // finish dots within each 8-lane group
#pragma unroll
        for (int mask = 1; mask <= 4; mask <<= 1)
#pragma unroll
            for (int c = 0; c < 8; c++)
                pd[c] += __shfl_xor_sync(0xffffffffu, pd[c], mask);

        if (MODE == 1) {
            pd[0] += b1a.x; pd[1] += b1a.y; pd[2] += b1a.z; pd[3] += b1a.w;
            pd[4] += b1b.x; pd[5] += b1b.y; pd[6] += b1b.z; pd[7] += b1b.w;
            if (ii + 1 < 16) {
                b1a = *(const float4*)(b1t + (ii + 1) * ONUM + g * 8);
                b1b = *(const float4*)(b1t + (ii + 1) * ONUM + g * 8 + 4);
            }
        } else {
            if (m == 0) *(float4*)(b1t + ii * ONUM + g * 8) =
                make_float4(pd[0], pd[1], pd[2], pd[3]);
            if (m == 1) *(float4*)(b1t + ii * ONUM + g * 8 + 4) =
                make_float4(pd[4], pd[5], pd[6], pd[7]);
        }

        // max-free softmax over 32 o's
#pragma unroll
        for (int c = 0; c < 8; c++) pd[c] = __expf(pd[c]);
        float sl = ((pd[0] + pd[1]) + (pd[2] + pd[3]))
                 + ((pd[4] + pd[5]) + (pd[6] + pd[7]));
        sl += __shfl_xor_sync(0xffffffffu, sl, 8);
        sl += __shfl_xor_sync(0xffffffffu, sl, 16);
        float inv = 1.0f / sl;

        // weighted accumulate (chunks re-streamed from smem)
#pragma unroll
        for (int c = 0; c < 8; c++) {
            float coef = pd[c] * inv;
            uint4 xv = stg[c * 32 + lane];
            const __half2* h = (const __half2*)&xv;
            float2 f0 = __half22float2(h[0]);
            float2 f1 = __half22float2(h[1]);
            float2 f2 = __half22float2(h[2]);
            float2 f3 = __half22float2(h[3]);
            sacc[c * 8 + 0] += coef * f0.x; sacc[c * 8 + 1] += coef * f0.y;
            sacc[c * 8 + 2] += coef * f1.x; sacc[c * 8 + 3] += coef * f1.y;
            sacc[c * 8 + 4] += coef * f2.x; sacc[c * 8 + 5] += coef * f2.y;
            sacc[c * 8 + 6] += coef * f3.x; sacc[c * 8 + 7] += coef * f3.y;
        }
    }

    // CTA reduction: lane (g,m), chunk c -> red[(c*4+g)][m*8+j]
#pragma unroll
    for (int c = 0; c < 8; c++)
#pragma unroll
        for (int j = 0; j < 8; j++)
            atomicAdd(&red[(c * 4 + g) * RED_S + m * 8 + j], sacc[c * 8 + j]);
    __syncthreads();

    for (int k = tid; k < OD; k += 128) {
        int o = k >> 6, d = k & 63;
        atomicAdd(&s_next[(size_t)b * OD + k], red[o * RED_S + d]);
    }
}

// ---------------- launch ------------------------------------------------------
extern "C" void kernel_launch(void* const* d_in, const int* in_sizes, int n_in,
                              void* d_out, int out_size)
{
    const float* x = (const float*)d_in[0];
    const float* w = (const float*)d_in[1];
    float* out = (float*)d_out;

    float* s_base;  cudaGetSymbolAddress((void**)&s_base,  g_s);
    float* s0 = s_base;
    float* s1 = s_base + BATCH * OD;
    float* s2 = s_base + 2 * BATCH * OD;

    cudaFuncSetAttribute(route_v11<0>, cudaFuncAttributeMaxDynamicSharedMemorySize, ROUTE_SMEM);
    cudaFuncSetAttribute(route_v11<1>, cudaFuncAttributeMaxDynamicSharedMemorySize, ROUTE_SMEM);

    zero_s_kernel<<<(3 * BATCH * OD + 255) / 256, 256>>>();

    gemm_xhat_hmma<<<dim3(16, 32), 256>>>(x, w);

    route_v11<0><<<dim3(BATCH, 8), 128, ROUTE_SMEM>>>(s0, s1);

    route_v11<1><<<dim3(BATCH, 8), 128, ROUTE_SMEM>>>(s1, s2);

    squash_kernel<<<(BATCH * ONUM) / 8, 256>>>(s2, out);
}

// round 14
// speedup vs baseline: 1.1006x; 1.1006x over previous
#include <cuda_runtime.h>
#include <cuda_fp16.h>
#include <cstdint>
#include <math.h>

#define BATCH 64
#define ONUM  32
#define INUM  512
#define DD    64
#define OD    2048               // ONUM*DD

// ---------------- scratch (device globals) -----------------------------------
__device__ __half g_xhat[(size_t)BATCH * INUM * OD];   // [b][i][o][d] fp16, 134MB
__device__ float g_s[3][BATCH * OD];
__device__ float g_out0[BATCH * OD];
__device__ float g_out1[BATCH * OD];
__device__ float g_b1[(size_t)BATCH * INUM * ONUM];    // permuted: [b][i][g*8+c]

// ---------------- helpers -----------------------------------------------------
__device__ __forceinline__ uint32_t smem_u32(const void* p) {
    uint32_t a;
    asm("{ .reg .u64 t; cvta.to.shared.u64 t, %1; cvt.u32.u64 %0, t; }" : "=r"(a) : "l"(p));
    return a;
}
__device__ __forceinline__ uint2 f4_to_h4(float4 v) {
    __half2 h0 = __floats2half2_rn(v.x, v.y);
    __half2 h1 = __floats2half2_rn(v.z, v.w);
    return make_uint2(*(uint32_t*)&h0, *(uint32_t*)&h1);
}
__device__ __forceinline__ uint32_t f2_to_h2(float a, float b) {
    __half2 h = __floats2half2_rn(a, b);
    return *(uint32_t*)&h;
}
__device__ __forceinline__ void ldmx4(uint32_t* r, uint32_t addr) {
    asm volatile("ldmatrix.sync.aligned.m8n8.x4.shared.b16 {%0,%1,%2,%3}, [%4];"
                 : "=r"(r[0]), "=r"(r[1]), "=r"(r[2]), "=r"(r[3]) : "r"(addr));
}
__device__ __forceinline__ void mma16816(float* c, const uint32_t* a, uint32_t b0, uint32_t b1) {
    asm volatile("mma.sync.aligned.m16n8k16.row.col.f32.f16.f16.f32 "
                 "{%0,%1,%2,%3}, {%4,%5,%6,%7}, {%8,%9}, {%0,%1,%2,%3};"
                 : "+f"(c[0]), "+f"(c[1]), "+f"(c[2]), "+f"(c[3])
                 : "r"(a[0]), "r"(a[1]), "r"(a[2]), "r"(a[3]), "r"(b0), "r"(b1));
}
__device__ __forceinline__ void cp16(uint32_t dst, const void* src) {
    asm volatile("cp.async.cg.shared.global [%0], [%1], 16;" :: "r"(dst), "l"(src));
}
#define CP_COMMIT() asm volatile("cp.async.commit_group;" ::: "memory")
#define CP_WAIT2()  asm volatile("cp.async.wait_group 2;" ::: "memory")

// ---------------- zero --------------------------------------------------------
__global__ void zero_s_kernel() {
    int idx = blockIdx.x * blockDim.x + threadIdx.x;
    if (idx < 3 * BATCH * OD) (&g_s[0][0])[idx] = 0.0f;
}

// ---------------- HMMA GEMM: x_hat + fused s0 (at DRAM roofline) --------------
#define WT_S 72
#define XT_S 72
#define OT_S 136

__global__ __launch_bounds__(256, 2) void gemm_xhat_hmma(
    const float* __restrict__ x, const float* __restrict__ w)
{
    __shared__ __align__(16) __half Wt[128 * WT_S];  // [od][m]
    __shared__ __align__(16) __half Xt[64 * XT_S];   // [b][m]
    __shared__ __align__(16) __half Ot[64 * OT_S];   // [b][od 0..127]

    const int tid = threadIdx.x, wid = tid >> 5, lane = tid & 31;
    const int p = blockIdx.x;
    const int ibase = blockIdx.y * 16;

    const uint32_t wbase = smem_u32(Wt);
    const uint32_t xbase = smem_u32(Xt);

    const float4* wf4 = (const float4*)w;
    const float4* xf4 = (const float4*)x;

    const int wm = wid & 1;
    const int wn = wid >> 1;
    const int r0a = wm * 32;
    const int n0  = wn * 32;

    const int a_row_off = (lane & 7) + ((lane >> 3) & 1) * 8;
    const int a_col_off = (lane >= 16) ? 8 : 0;
    const int b_row_off = (lane & 7) + ((lane >> 4) & 1) * 8;
    const int b_col_off = ((lane >> 3) & 1) * 8;

    float s0acc[4][8];
#pragma unroll
    for (int j = 0; j < 4; j++)
#pragma unroll
        for (int e = 0; e < 8; e++) s0acc[j][e] = 0.0f;

    for (int t = 0; t < 16; t++) {
        const int i = ibase + t;

#pragma unroll
        for (int k = 0; k < 8; k++) {
            int g = tid + k * 256;
            int ol = g >> 10, rem = g & 1023;
            float4 v = wf4[(((size_t)(2 * p + ol) * INUM + i) << 10) + rem];
            *(uint2*)&Wt[(ol * 64 + (rem >> 4)) * WT_S + (rem & 15) * 4] = f4_to_h4(v);
        }
#pragma unroll
        for (int j = 0; j < 4; j++) {
            int idx = tid + j * 256;
            int b = idx >> 4, mq = idx & 15;
            float4 v = xf4[((size_t)b * INUM + i) * 16 + mq];
            *(uint2*)&Xt[b * XT_S + mq * 4] = f4_to_h4(v);
        }
        __syncthreads();

        float acc[2][4][4];
#pragma unroll
        for (int mt = 0; mt < 2; mt++)
#pragma unroll
            for (int nt = 0; nt < 4; nt++)
#pragma unroll
                for (int e = 0; e < 4; e++) acc[mt][nt][e] = 0.0f;

#pragma unroll
        for (int ks = 0; ks < 4; ks++) {
            const int kc = ks * 16;
            uint32_t afr[2][4], bfr[2][4];
#pragma unroll
            for (int mt = 0; mt < 2; mt++) {
                int row = r0a + mt * 16 + a_row_off;
                int col = kc + a_col_off;
                ldmx4(afr[mt], xbase + (row * XT_S + col) * 2);
            }
#pragma unroll
            for (int nt2 = 0; nt2 < 2; nt2++) {
                int row = n0 + nt2 * 16 + b_row_off;
                int col = kc + b_col_off;
                ldmx4(bfr[nt2], wbase + (row * WT_S + col) * 2);
            }
#pragma unroll
            for (int mt = 0; mt < 2; mt++) {
#pragma unroll
                for (int nt = 0; nt < 4; nt++) {
                    uint32_t b0 = bfr[nt >> 1][(nt & 1) * 2 + 0];
                    uint32_t b1 = bfr[nt >> 1][(nt & 1) * 2 + 1];
                    mma16816(acc[mt][nt], afr[mt], b0, b1);
                }
            }
        }

#pragma unroll
        for (int mt = 0; mt < 2; mt++) {
            int row = r0a + mt * 16 + (lane >> 2);
#pragma unroll
            for (int nt = 0; nt < 4; nt++) {
                int col = n0 + nt * 8 + (lane & 3) * 2;
                *(uint32_t*)&Ot[row * OT_S + col] = f2_to_h2(acc[mt][nt][0], acc[mt][nt][1]);
                *(uint32_t*)&Ot[(row + 8) * OT_S + col] = f2_to_h2(acc[mt][nt][2], acc[mt][nt][3]);
            }
        }
        __syncthreads();

#pragma unroll
        for (int j = 0; j < 4; j++) {
            int idx = tid + j * 256;
            int brow = idx >> 4, chunk = idx & 15;
            uint4 v = *(const uint4*)&Ot[brow * OT_S + chunk * 8];
            const __half2* h = (const __half2*)&v;
#pragma unroll
            for (int q = 0; q < 4; q++) {
                float2 f = __half22float2(h[q]);
                s0acc[j][q * 2 + 0] += f.x;
                s0acc[j][q * 2 + 1] += f.y;
            }
            *(uint4*)&g_xhat[((size_t)brow * INUM + i) * OD + p * 128 + chunk * 8] = v;
        }
        __syncthreads();
    }

    const float sc = 1.0f / (float)ONUM;
#pragma unroll
    for (int j = 0; j < 4; j++) {
        int idx = tid + j * 256;
        int brow = idx >> 4, chunk = idx & 15;
        float* sp = &g_s[0][brow * OD + p * 128 + chunk * 8];
#pragma unroll
        for (int e = 0; e < 8; e++)
            atomicAdd(sp + e, s0acc[j][e] * sc);
    }
}

// ---------------- squash ------------------------------------------------------
__global__ void squash_kernel(const float* __restrict__ s, float* __restrict__ v)
{
    int gw   = (blockIdx.x * blockDim.x + threadIdx.x) >> 5;
    int lane = threadIdx.x & 31;
    if (gw >= BATCH * ONUM) return;
    const float* row = s + (size_t)gw * 64;
    float a = row[lane];
    float b = row[lane + 32];
    float ss = a * a + b * b;
#pragma unroll
    for (int off = 16; off; off >>= 1) ss += __shfl_xor_sync(0xffffffffu, ss, off);
    float n = sqrtf(ss);
    float f = (ss / (1.0f + ss)) / (n + 1e-8f);
    v[(size_t)gw * 64 + lane]      = a * f;
    v[(size_t)gw * 64 + lane + 32] = b * f;
}

// ---------------- routing pass v12: v10 inner loop, 1-warp CTAs ---------------
// grid (64,16), block 32. CTA = one warp = (b, 32 i's). Identical streaming
// loop to v10 (coalesced cp.async 4-stage ring, depth-3 lead, half2 opv,
// group-shuffle dot, max-free softmax, b1 prefetch). Epilogue: direct global
// atomics (no smem reduction, no barriers).
#define RING_BYTES 16384                     // 4 stages * 4KB

template <int MODE>
__global__ __launch_bounds__(32) void route_v12(
    const float* __restrict__ out_prev, float* __restrict__ s_next)
{
    extern __shared__ __align__(16) char dsm[];

    const int lane = threadIdx.x & 31;
    const int g = lane >> 3, m = lane & 7;
    const int b = blockIdx.x;
    const int i0 = blockIdx.y * 32;

    const uint4* xp = (const uint4*)(g_xhat + ((size_t)b * INUM + i0) * OD);
    const uint32_t ringbase = smem_u32(dsm);
    const char* ringptr = dsm;

    // prologue: issue stages 0..2 (coalesced: 512B contiguous per instr, both sides)
#pragma unroll
    for (int t = 0; t < 3; t++) {
        const uint4* src = xp + t * 256;
        uint32_t dst = ringbase + t * 4096;
#pragma unroll
        for (int c = 0; c < 8; c++)
            cp16(dst + (c * 32 + lane) * 16, src + c * 32 + lane);
        CP_COMMIT();
    }

    // opvh[c*4+q] = half2(out_prev[b][c*4+g][m*8+2q], ..+1)
    uint32_t opvh[32];
    {
        const float* opb = out_prev + (size_t)b * OD;
#pragma unroll
        for (int c = 0; c < 8; c++) {
            const float* q = opb + (c * 4 + g) * 64 + m * 8;
            float4 v0 = *(const float4*)q;
            float4 v1 = *(const float4*)(q + 4);
            opvh[c * 4 + 0] = f2_to_h2(v0.x, v0.y);
            opvh[c * 4 + 1] = f2_to_h2(v0.z, v0.w);
            opvh[c * 4 + 2] = f2_to_h2(v1.x, v1.y);
            opvh[c * 4 + 3] = f2_to_h2(v1.z, v1.w);
        }
    }

    float sacc[64];
#pragma unroll
    for (int d = 0; d < 64; d++) sacc[d] = 0.0f;

    float* b1t = g_b1 + ((size_t)b * INUM + i0) * ONUM;   // [i][g*8+c]
    float4 b1a, b1b;
    if (MODE == 1) {
        b1a = *(const float4*)(b1t + g * 8);
        b1b = *(const float4*)(b1t + g * 8 + 4);
    }

    for (int ii = 0; ii < 32; ii++) {
        CP_WAIT2();   // 3-pending invariant -> stage ii complete

        const uint4* stg = (const uint4*)(ringptr + (ii & 3) * 4096);
        uint4 cur[8];
#pragma unroll
        for (int c = 0; c < 8; c++) cur[c] = stg[c * 32 + lane];

        // issue stage ii+3 (dummy commit keeps pending invariant)
        if (ii + 3 < 32) {
            const uint4* src = xp + (size_t)(ii + 3) * 256;
            uint32_t dst = ringbase + ((ii + 3) & 3) * 4096;
#pragma unroll
            for (int c = 0; c < 8; c++)
                cp16(dst + (c * 32 + lane) * 16, src + c * 32 + lane);
        }
        CP_COMMIT();

        // partial dots pd[c] = <chunk c, opv[c]>
        float pd[8];
#pragma unroll
        for (int c = 0; c < 8; c++) {
            const __half2* h = (const __half2*)&cur[c];
            float2 f0 = __half22float2(h[0]);
            float2 f1 = __half22float2(h[1]);
            float2 f2 = __half22float2(h[2]);
            float2 f3 = __half22float2(h[3]);
            float2 o0 = __half22float2(*(const __half2*)&opvh[c * 4 + 0]);
            float2 o1 = __half22float2(*(const __half2*)&opvh[c * 4 + 1]);
            float2 o2 = __half22float2(*(const __half2*)&opvh[c * 4 + 2]);
            float2 o3 = __half22float2(*(const __half2*)&opvh[c * 4 + 3]);
            pd[c] = f0.x * o0.x + f0.y * o0.y + f1.x * o1.x + f1.y * o1.y
                  + f2.x * o2.x + f2.y * o2.y + f3.x * o3.x + f3.y * o3.y;
        }
        // finish dots within each 8-lane group
#pragma unroll
        for (int mask = 1; mask <= 4; mask <<= 1)
#pragma unroll
            for (int c = 0; c < 8; c++)
                pd[c] += __shfl_xor_sync(0xffffffffu, pd[c], mask);

        if (MODE == 1) {
            pd[0] += b1a.x; pd[1] += b1a.y; pd[2] += b1a.z; pd[3] += b1a.w;
            pd[4] += b1b.x; pd[5] += b1b.y; pd[6] += b1b.z; pd[7] += b1b.w;
            if (ii + 1 < 32) {
                b1a = *(const float4*)(b1t + (ii + 1) * ONUM + g * 8);
                b1b = *(const float4*)(b1t + (ii + 1) * ONUM + g * 8 + 4);
            }
        } else {
            if (m == 0) *(float4*)(b1t + ii * ONUM + g * 8) =
                make_float4(pd[0], pd[1], pd[2], pd[3]);
            if (m == 1) *(float4*)(b1t + ii * ONUM + g * 8 + 4) =
                make_float4(pd[4], pd[5], pd[6], pd[7]);
        }

        // max-free softmax over 32 o's
#pragma unroll
        for (int c = 0; c < 8; c++) pd[c] = __expf(pd[c]);
        float sl = ((pd[0] + pd[1]) + (pd[2] + pd[3]))
                 + ((pd[4] + pd[5]) + (pd[6] + pd[7]));
        sl += __shfl_xor_sync(0xffffffffu, sl, 8);
        sl += __shfl_xor_sync(0xffffffffu, sl, 16);
        float inv = 1.0f / sl;

        // weighted accumulate
#pragma unroll
        for (int c = 0; c < 8; c++) {
            float coef = pd[c] * inv;
            const __half2* h = (const __half2*)&cur[c];
            float2 f0 = __half22float2(h[0]);
            float2 f1 = __half22float2(h[1]);
            float2 f2 = __half22float2(h[2]);
            float2 f3 = __half22float2(h[3]);
            sacc[c * 8 + 0] += coef * f0.x; sacc[c * 8 + 1] += coef * f0.y;
            sacc[c * 8 + 2] += coef * f1.x; sacc[c * 8 + 3] += coef * f1.y;
            sacc[c * 8 + 4] += coef * f2.x; sacc[c * 8 + 5] += coef * f2.y;
            sacc[c * 8 + 6] += coef * f3.x; sacc[c * 8 + 7] += coef * f3.y;
        }
    }

    // epilogue: direct global atomics (no-return REDG; spread addresses)
    float* sb = s_next + (size_t)b * OD;
#pragma unroll
    for (int c = 0; c < 8; c++)
#pragma unroll
        for (int j = 0; j < 8; j++)
            atomicAdd(sb + (c * 4 + g) * 64 + m * 8 + j, sacc[c * 8 + j]);
}

// ---------------- launch ------------------------------------------------------
extern "C" void kernel_launch(void* const* d_in, const int* in_sizes, int n_in,
                              void* d_out, int out_size)
{
    const float* x = (const float*)d_in[0];
    const float* w = (const float*)d_in[1];
    float* out = (float*)d_out;

    float* s_base;  cudaGetSymbolAddress((void**)&s_base,  g_s);
    float* out0;    cudaGetSymbolAddress((void**)&out0,    g_out0);
    float* out1;    cudaGetSymbolAddress((void**)&out1,    g_out1);
    float* s0 = s_base;
    float* s1 = s_base + BATCH * OD;
    float* s2 = s_base + 2 * BATCH * OD;

    cudaFuncSetAttribute(route_v12<0>, cudaFuncAttributeMaxDynamicSharedMemorySize, RING_BYTES);
    cudaFuncSetAttribute(route_v12<1>, cudaFuncAttributeMaxDynamicSharedMemorySize, RING_BYTES);

    zero_s_kernel<<<(3 * BATCH * OD + 255) / 256, 256>>>();

    gemm_xhat_hmma<<<dim3(16, 32), 256>>>(x, w);

    squash_kernel<<<(BATCH * ONUM) / 8, 256>>>(s0, out0);

    route_v12<0><<<dim3(BATCH, 16), 32, RING_BYTES>>>(out0, s1);

    squash_kernel<<<(BATCH * ONUM) / 8, 256>>>(s1, out1);

    route_v12<1><<<dim3(BATCH, 16), 32, RING_BYTES>>>(out1, s2);

    squash_kernel<<<(BATCH * ONUM) / 8, 256>>>(s2, out);
}

// round 17
// speedup vs baseline: 1.1917x; 1.0828x over previous
#include <cuda_runtime.h>
#include <cuda_fp16.h>
#include <cstdint>
#include <math.h>

#define BATCH 64
#define ONUM  32
#define INUM  512
#define DD    64
#define OD    2048               // ONUM*DD

// ---------------- scratch (device globals) -----------------------------------
__device__ __half g_xhat[(size_t)BATCH * INUM * OD];   // [b][i][o][d] fp16, 134MB
__device__ float g_s[3][BATCH * OD];
__device__ float g_out0[BATCH * OD];
__device__ float g_out1[BATCH * OD];
__device__ float g_b1[(size_t)BATCH * INUM * ONUM];    // permuted: [b][i][g*8+c]

// ---------------- helpers -----------------------------------------------------
__device__ __forceinline__ uint32_t smem_u32(const void* p) {
    uint32_t a;
    asm("{ .reg .u64 t; cvta.to.shared.u64 t, %1; cvt.u32.u64 %0, t; }" : "=r"(a) : "l"(p));
    return a;
}
__device__ __forceinline__ uint2 f4_to_h4(float4 v) {
    __half2 h0 = __floats2half2_rn(v.x, v.y);
    __half2 h1 = __floats2half2_rn(v.z, v.w);
    return make_uint2(*(uint32_t*)&h0, *(uint32_t*)&h1);
}
__device__ __forceinline__ uint32_t f2_to_h2(float a, float b) {
    __half2 h = __floats2half2_rn(a, b);
    return *(uint32_t*)&h;
}
__device__ __forceinline__ void ldmx4(uint32_t* r, uint32_t addr) {
    asm volatile("ldmatrix.sync.aligned.m8n8.x4.shared.b16 {%0,%1,%2,%3}, [%4];"
                 : "=r"(r[0]), "=r"(r[1]), "=r"(r[2]), "=r"(r[3]) : "r"(addr));
}
__device__ __forceinline__ void mma16816(float* c, const uint32_t* a, uint32_t b0, uint32_t b1) {
    asm volatile("mma.sync.aligned.m16n8k16.row.col.f32.f16.f16.f32 "
                 "{%0,%1,%2,%3}, {%4,%5,%6,%7}, {%8,%9}, {%0,%1,%2,%3};"
                 : "+f"(c[0]), "+f"(c[1]), "+f"(c[2]), "+f"(c[3])
                 : "r"(a[0]), "r"(a[1]), "r"(a[2]), "r"(a[3]), "r"(b0), "r"(b1));
}
__device__ __forceinline__ void cp16(uint32_t dst, const void* src) {
    asm volatile("cp.async.cg.shared.global [%0], [%1], 16;" :: "r"(dst), "l"(src));
}
#define CP_COMMIT() asm volatile("cp.async.commit_group;" ::: "memory")
#define CP_WAIT2()  asm volatile("cp.async.wait_group 2;" ::: "memory")

// ---------------- zero --------------------------------------------------------
__global__ void zero_s_kernel() {
    int idx = blockIdx.x * blockDim.x + threadIdx.x;
    if (idx < 3 * BATCH * OD) (&g_s[0][0])[idx] = 0.0f;
}

// ---------------- HMMA GEMM: x_hat + fused s0 (at DRAM roofline) --------------
#define WT_S 72
#define XT_S 72
#define OT_S 136

__global__ __launch_bounds__(256, 2) void gemm_xhat_hmma(
    const float* __restrict__ x, const float* __restrict__ w)
{
    __shared__ __align__(16) __half Wt[128 * WT_S];  // [od][m]
    __shared__ __align__(16) __half Xt[64 * XT_S];   // [b][m]
    __shared__ __align__(16) __half Ot[64 * OT_S];   // [b][od 0..127]

    const int tid = threadIdx.x, wid = tid >> 5, lane = tid & 31;
    const int p = blockIdx.x;
    const int ibase = blockIdx.y * 16;

    const uint32_t wbase = smem_u32(Wt);
    const uint32_t xbase = smem_u32(Xt);

    const float4* wf4 = (const float4*)w;
    const float4* xf4 = (const float4*)x;

    const int wm = wid & 1;
    const int wn = wid >> 1;
    const int r0a = wm * 32;
    const int n0  = wn * 32;

    const int a_row_off = (lane & 7) + ((lane >> 3) & 1) * 8;
    const int a_col_off = (lane >= 16) ? 8 : 0;
    const int b_row_off = (lane & 7) + ((lane >> 4) & 1) * 8;
    const int b_col_off = ((lane >> 3) & 1) * 8;

    float s0acc[4][8];
#pragma unroll
    for (int j = 0; j < 4; j++)
#pragma unroll
        for (int e = 0; e < 8; e++) s0acc[j][e] = 0.0f;

    for (int t = 0; t < 16; t++) {
        const int i = ibase + t;

#pragma unroll
        for (int k = 0; k < 8; k++) {
            int g = tid + k * 256;
            int ol = g >> 10, rem = g & 1023;
            float4 v = wf4[(((size_t)(2 * p + ol) * INUM + i) << 10) + rem];
            *(uint2*)&Wt[(ol * 64 + (rem >> 4)) * WT_S + (rem & 15) * 4] = f4_to_h4(v);
        }
#pragma unroll
        for (int j = 0; j < 4; j++) {
            int idx = tid + j * 256;
            int b = idx >> 4, mq = idx & 15;
            float4 v = xf4[((size_t)b * INUM + i) * 16 + mq];
            *(uint2*)&Xt[b * XT_S + mq * 4] = f4_to_h4(v);
        }
        __syncthreads();

        float acc[2][4][4];
#pragma unroll
        for (int mt = 0; mt < 2; mt++)
#pragma unroll
            for (int nt = 0; nt < 4; nt++)
#pragma unroll
                for (int e = 0; e < 4; e++) acc[mt][nt][e] = 0.0f;

#pragma unroll
        for (int ks = 0; ks < 4; ks++) {
            const int kc = ks * 16;
            uint32_t afr[2][4], bfr[2][4];
#pragma unroll
            for (int mt = 0; mt < 2; mt++) {
                int row = r0a + mt * 16 + a_row_off;
                int col = kc + a_col_off;
                ldmx4(afr[mt], xbase + (row * XT_S + col) * 2);
            }
#pragma unroll
            for (int nt2 = 0; nt2 < 2; nt2++) {
                int row = n0 + nt2 * 16 + b_row_off;
                int col = kc + b_col_off;
                ldmx4(bfr[nt2], wbase + (row * WT_S + col) * 2);
            }
#pragma unroll
            for (int mt = 0; mt < 2; mt++) {
#pragma unroll
                for (int nt = 0; nt < 4; nt++) {
                    uint32_t b0 = bfr[nt >> 1][(nt & 1) * 2 + 0];
                    uint32_t b1 = bfr[nt >> 1][(nt & 1) * 2 + 1];
                    mma16816(acc[mt][nt], afr[mt], b0, b1);
                }
            }
        }

#pragma unroll
        for (int mt = 0; mt < 2; mt++) {
            int row = r0a + mt * 16 + (lane >> 2);
#pragma unroll
            for (int nt = 0; nt < 4; nt++) {
                int col = n0 + nt * 8 + (lane & 3) * 2;
                *(uint32_t*)&Ot[row * OT_S + col] = f2_to_h2(acc[mt][nt][0], acc[mt][nt][1]);
                *(uint32_t*)&Ot[(row + 8) * OT_S + col] = f2_to_h2(acc[mt][nt][2], acc[mt][nt][3]);
            }
        }
        __syncthreads();

#pragma unroll
        for (int j = 0; j < 4; j++) {
            int idx = tid + j * 256;
            int brow = idx >> 4, chunk = idx & 15;
            uint4 v = *(const uint4*)&Ot[brow * OT_S + chunk * 8];
            const __half2* h = (const __half2*)&v;
#pragma unroll
            for (int q = 0; q < 4; q++) {
                float2 f = __half22float2(h[q]);
                s0acc[j][q * 2 + 0] += f.x;
                s0acc[j][q * 2 + 1] += f.y;
            }
            *(uint4*)&g_xhat[((size_t)brow * INUM + i) * OD + p * 128 + chunk * 8] = v;
        }
        __syncthreads();
    }

    const float sc = 1.0f / (float)ONUM;
#pragma unroll
    for (int j = 0; j < 4; j++) {
        int idx = tid + j * 256;
        int brow = idx >> 4, chunk = idx & 15;
        float* sp = &g_s[0][brow * OD + p * 128 + chunk * 8];
#pragma unroll
        for (int e = 0; e < 8; e++)
            atomicAdd(sp + e, s0acc[j][e] * sc);
    }
}

// ---------------- squash ------------------------------------------------------
__global__ void squash_kernel(const float* __restrict__ s, float* __restrict__ v)
{
    int gw   = (blockIdx.x * blockDim.x + threadIdx.x) >> 5;
    int lane = threadIdx.x & 31;
    if (gw >= BATCH * ONUM) return;
    const float* row = s + (size_t)gw * 64;
    float a = row[lane];
    float b = row[lane + 32];
    float ss = a * a + b * b;
#pragma unroll
    for (int off = 16; off; off >>= 1) ss += __shfl_xor_sync(0xffffffffu, ss, off);
    float n = sqrtf(ss);
    float f = (ss / (1.0f + ss)) / (n + 1e-8f);
    v[(size_t)gw * 64 + lane]      = a * f;
    v[(size_t)gw * 64 + lane + 32] = b * f;
}

// ---------------- routing pass v13: v10 + fp32 opv (64 fewer CVT/iter) --------
// grid (64,4), block 128 (4 warps). warp -> (b, 32 i's).
// Coalesced cp.async 4-stage ring (depth-3 lead), group-shuffle dot,
// max-free softmax, b1 prefetch. opv now fp32 registers (converted once).
#define RED_S 65
#define WARP_RING 16384                      // 4 stages * 4KB
#define ROUTE_SMEM (4 * WARP_RING + ONUM * RED_S * 4)

template <int MODE>
__global__ __launch_bounds__(128) void route_v13(
    const float* __restrict__ out_prev, float* __restrict__ s_next)
{
    extern __shared__ __align__(16) char dsm[];
    float* red = (float*)(dsm + 4 * WARP_RING);

    const int tid = threadIdx.x, wid = tid >> 5, lane = tid & 31;
    const int g = lane >> 3, m = lane & 7;
    const int b = blockIdx.x;
    const int i0 = (blockIdx.y * 4 + wid) * 32;

    const uint4* xp = (const uint4*)(g_xhat + ((size_t)b * INUM + i0) * OD);
    const uint32_t ringbase = smem_u32(dsm) + wid * WARP_RING;
    const char* ringptr = dsm + wid * WARP_RING;

    // prologue: issue stages 0..2 (coalesced: 512B contiguous per instr)
#pragma unroll
    for (int t = 0; t < 3; t++) {
        const uint4* src = xp + t * 256;
        uint32_t dst = ringbase + t * 4096;
#pragma unroll
        for (int c = 0; c < 8; c++)
            cp16(dst + (c * 32 + lane) * 16, src + c * 32 + lane);
        CP_COMMIT();
    }

    for (int k = tid; k < ONUM * RED_S; k += 128) red[k] = 0.0f;

    // opv[c*8+j] = out_prev[b][o=c*4+g][m*8+j]  (fp32, converted zero times/iter)
    float opv[64];
    {
        const float* opb = out_prev + (size_t)b * OD;
#pragma unroll
        for (int c = 0; c < 8; c++) {
            const float* q = opb + (c * 4 + g) * 64 + m * 8;
            float4 v0 = *(const float4*)q;
            float4 v1 = *(const float4*)(q + 4);
            opv[c * 8 + 0] = v0.x; opv[c * 8 + 1] = v0.y;
            opv[c * 8 + 2] = v0.z; opv[c * 8 + 3] = v0.w;
            opv[c * 8 + 4] = v1.x; opv[c * 8 + 5] = v1.y;
            opv[c * 8 + 6] = v1.z; opv[c * 8 + 7] = v1.w;
        }
    }
    __syncthreads();   // red zeroed

    float sacc[64];
#pragma unroll
    for (int d = 0; d < 64; d++) sacc[d] = 0.0f;

    float* b1t = g_b1 + ((size_t)b * INUM + i0) * ONUM;   // [i][g*8+c]
    float4 b1a, b1b;
    if (MODE == 1) {
        b1a = *(const float4*)(b1t + g * 8);
        b1b = *(const float4*)(b1t + g * 8 + 4);
    }

    for (int ii = 0; ii < 32; ii++) {
        CP_WAIT2();   // 3-pending invariant -> stage ii complete

        const uint4* stg = (const uint4*)(ringptr + (ii & 3) * 4096);
        uint4 cur[8];
#pragma unroll
        for (int c = 0; c < 8; c++) cur[c] = stg[c * 32 + lane];

        // issue stage ii+3 (dummy commit keeps pending invariant)
        if (ii + 3 < 32) {
            const uint4* src = xp + (size_t)(ii + 3) * 256;
            uint32_t dst = ringbase + ((ii + 3) & 3) * 4096;
#pragma unroll
            for (int c = 0; c < 8; c++)
                cp16(dst + (c * 32 + lane) * 16, src + c * 32 + lane);
        }
        CP_COMMIT();

        // partial dots pd[c] = <chunk c, opv[c]>  (only x needs conversion)
        float pd[8];
#pragma unroll
        for (int c = 0; c < 8; c++) {
            const __half2* h = (const __half2*)&cur[c];
            float2 f0 = __half22float2(h[0]);
            float2 f1 = __half22float2(h[1]);
            float2 f2 = __half22float2(h[2]);
            float2 f3 = __half22float2(h[3]);
            pd[c] = f0.x * opv[c * 8 + 0] + f0.y * opv[c * 8 + 1]
                  + f1.x * opv[c * 8 + 2] + f1.y * opv[c * 8 + 3]
                  + f2.x * opv[c * 8 + 4] + f2.y * opv[c * 8 + 5]
                  + f3.x * opv[c * 8 + 6] + f3.y * opv[c * 8 + 7];
        }
        // finish dots within each 8-lane group
#pragma unroll
        for (int mask = 1; mask <= 4; mask <<= 1)
#pragma unroll
            for (int c = 0; c < 8; c++)
                pd[c] += __shfl_xor_sync(0xffffffffu, pd[c], mask);

        if (MODE == 1) {
            pd[0] += b1a.x; pd[1] += b1a.y; pd[2] += b1a.z; pd[3] += b1a.w;
            pd[4] += b1b.x; pd[5] += b1b.y; pd[6] += b1b.z; pd[7] += b1b.w;
            if (ii + 1 < 32) {
                b1a = *(const float4*)(b1t + (ii + 1) * ONUM + g * 8);
                b1b = *(const float4*)(b1t + (ii + 1) * ONUM + g * 8 + 4);
            }
        } else {
            if (m == 0) *(float4*)(b1t + ii * ONUM + g * 8) =
                make_float4(pd[0], pd[1], pd[2], pd[3]);
            if (m == 1) *(float4*)(b1t + ii * ONUM + g * 8 + 4) =
                make_float4(pd[4], pd[5], pd[6], pd[7]);
        }

        // max-free softmax over 32 o's
#pragma unroll
        for (int c = 0; c < 8; c++) pd[c] = __expf(pd[c]);
        float sl = ((pd[0] + pd[1]) + (pd[2] + pd[3]))
                 + ((pd[4] + pd[5]) + (pd[6] + pd[7]));
        sl += __shfl_xor_sync(0xffffffffu, sl, 8);
        sl += __shfl_xor_sync(0xffffffffu, sl, 16);
        float inv = 1.0f / sl;

        // weighted accumulate
#pragma unroll
        for (int c = 0; c < 8; c++) {
            float coef = pd[c] * inv;
            const __half2* h = (const __half2*)&cur[c];
            float2 f0 = __half22float2(h[0]);
            float2 f1 = __half22float2(h[1]);
            float2 f2 = __half22float2(h[2]);
            float2 f3 = __half22float2(h[3]);
            sacc[c * 8 + 0] += coef * f0.x; sacc[c * 8 + 1] += coef * f0.y;
            sacc[c * 8 + 2] += coef * f1.x; sacc[c * 8 + 3] += coef * f1.y;
            sacc[c * 8 + 4] += coef * f2.x; sacc[c * 8 + 5] += coef * f2.y;
            sacc[c * 8 + 6] += coef * f3.x; sacc[c * 8 + 7] += coef * f3.y;
        }
    }

    // CTA reduction: lane (g,m), chunk c -> red[(c*4+g)][m*8+j]
#pragma unroll
    for (int c = 0; c < 8; c++)
#pragma unroll
        for (int j = 0; j < 8; j++)
            atomicAdd(&red[(c * 4 + g) * RED_S + m * 8 + j], sacc[c * 8 + j]);
    __syncthreads();

    for (int k = tid; k < OD; k += 128) {
        int o = k >> 6, d = k & 63;
        atomicAdd(&s_next[(size_t)b * OD + k], red[o * RED_S + d]);
    }
}

// ---------------- launch ------------------------------------------------------
extern "C" void kernel_launch(void* const* d_in, const int* in_sizes, int n_in,
                              void* d_out, int out_size)
{
    const float* x = (const float*)d_in[0];
    const float* w = (const float*)d_in[1];
    float* out = (float*)d_out;

    float* s_base;  cudaGetSymbolAddress((void**)&s_base,  g_s);
    float* out0;    cudaGetSymbolAddress((void**)&out0,    g_out0);
    float* out1;    cudaGetSymbolAddress((void**)&out1,    g_out1);
    float* s0 = s_base;
    float* s1 = s_base + BATCH * OD;
    float* s2 = s_base + 2 * BATCH * OD;

    cudaFuncSetAttribute(route_v13<0>, cudaFuncAttributeMaxDynamicSharedMemorySize, ROUTE_SMEM);
    cudaFuncSetAttribute(route_v13<1>, cudaFuncAttributeMaxDynamicSharedMemorySize, ROUTE_SMEM);

    zero_s_kernel<<<(3 * BATCH * OD + 255) / 256, 256>>>();

    gemm_xhat_hmma<<<dim3(16, 32), 256>>>(x, w);

    squash_kernel<<<(BATCH * ONUM) / 8, 256>>>(s0, out0);

    route_v13<0><<<dim3(BATCH, 4), 128, ROUTE_SMEM>>>(out0, s1);

    squash_kernel<<<(BATCH * ONUM) / 8, 256>>>(s1, out1);

    route_v13<1><<<dim3(BATCH, 4), 128, ROUTE_SMEM>>>(out1, s2);

    squash_kernel<<<(BATCH * ONUM) / 8, 256>>>(s2, out);
}